// round 3
// baseline (speedup 1.0000x reference)
#include <cuda_runtime.h>
#include <cstdint>

// ---------------------------------------------------------------------------
// SimpleLSTM on GB300 (sm_103a) — round 3: clustered DSMEM recurrence.
//
//   kernel 1 (table_kernel): token table T[v][g] = E[v] . W_x^T + b for the
//       768 LIVE gate rows (F, O, Htmp; I gate is dead code).
//   kernel 2 (lstm_kernel): 16 clusters x 8 CTAs. Cluster c owns batch rows
//       8c..8c+7; CTA rank r owns hidden cols 32r..32r+31 and its 96x256 W_h
//       slice in SMEM. Per step each CTA pushes its 8x32 H_new slice into all
//       8 cluster peers' SMEM (st.shared::cluster) and signals via a local
//       mbarrier (release/acquire at cluster scope). No global memory on the
//       recurrent path.
// ---------------------------------------------------------------------------

#define NB    128
#define LSEQ  2048
#define HDIM  256
#define EMB   256
#define VOC   32000
#define G3    768

__device__ float g_T[VOC * G3];      // token-gate table (~98.3 MB)

// ---------------------------------------------------------------------------
// helpers
// ---------------------------------------------------------------------------
__device__ __forceinline__ unsigned long long ffma2(unsigned long long a,
                                                    unsigned long long b,
                                                    unsigned long long c)
{
    unsigned long long d;
    asm("fma.rn.f32x2 %0, %1, %2, %3;" : "=l"(d) : "l"(a), "l"(b), "l"(c));
    return d;
}

__device__ __forceinline__ float2 ull2f2(unsigned long long v)
{
    float2 f;
    asm("mov.b64 {%0, %1}, %2;" : "=f"(f.x), "=f"(f.y) : "l"(v));
    return f;
}

__device__ __forceinline__ uint32_t smem_u32(const void* p)
{
    uint32_t a;
    asm("{ .reg .u64 t; cvta.to.shared.u64 t, %1; cvt.u32.u64 %0, t; }"
        : "=r"(a) : "l"(p));
    return a;
}

__device__ __forceinline__ uint32_t ctarank()
{
    uint32_t r;
    asm("mov.u32 %0, %%cluster_ctarank;" : "=r"(r));
    return r;
}

__device__ __forceinline__ uint32_t mapa_u32(uint32_t laddr, uint32_t rank)
{
    uint32_t r;
    asm("mapa.shared::cluster.u32 %0, %1, %2;" : "=r"(r) : "r"(laddr), "r"(rank));
    return r;
}

__device__ __forceinline__ void st_cluster_128(uint32_t addr, float4 v)
{
    asm volatile("st.shared::cluster.v4.f32 [%0], {%1, %2, %3, %4};"
                 :: "r"(addr), "f"(v.x), "f"(v.y), "f"(v.z), "f"(v.w)
                 : "memory");
}

__device__ __forceinline__ void mbar_init(uint32_t addr, uint32_t count)
{
    asm volatile("mbarrier.init.shared.b64 [%0], %1;" :: "r"(addr), "r"(count)
                 : "memory");
}

// arrive on the same-offset mbarrier in cluster CTA `rank` (release.cluster)
__device__ __forceinline__ void mbar_arrive_rank(uint32_t laddr, uint32_t rank)
{
    asm volatile(
        "{ .reg .b32 ra; mapa.shared::cluster.u32 ra, %0, %1;\n\t"
        "  mbarrier.arrive.release.cluster.shared::cluster.b64 _, [ra]; }"
        :: "r"(laddr), "r"(rank) : "memory");
}

__device__ __forceinline__ void mbar_wait_parity_cluster(uint32_t addr,
                                                         uint32_t parity)
{
    uint32_t done = 0;
    while (!done) {
        asm volatile(
            "{ .reg .pred p;\n\t"
            "  mbarrier.try_wait.parity.acquire.cluster.shared::cta.b64 p, [%1], %2, 0x989680;\n\t"
            "  selp.b32 %0, 1, 0, p; }"
            : "=r"(done) : "r"(addr), "r"(parity) : "memory");
    }
}

__device__ __forceinline__ void cluster_sync_()
{
    asm volatile("barrier.cluster.arrive.aligned;" ::: "memory");
    asm volatile("barrier.cluster.wait.aligned;" ::: "memory");
}

__device__ __forceinline__ float sig_fast(float x)
{
    return __fdividef(1.0f, 1.0f + __expf(-x));
}

__device__ __forceinline__ float tanh_fast(float x)
{
    return __fdividef(2.0f, 1.0f + __expf(-2.0f * x)) - 1.0f;
}

// ---------------------------------------------------------------------------
// Kernel 1: token table GEMM (M=32000, N=768 live gates, K=256)
// ---------------------------------------------------------------------------
__global__ void table_kernel(const float* __restrict__ E,
                             const float* __restrict__ Ww,
                             const float* __restrict__ Wb)
{
    __shared__ float Esm[32][68];
    __shared__ float Wsm[32][68];

    const int tid = threadIdx.x;
    const int v0  = blockIdx.x * 64;
    const int g0  = blockIdx.y * 64;

    const int tx = tid & 15;
    const int ty = tid >> 4;

    float acc[4][4];
#pragma unroll
    for (int i = 0; i < 4; i++)
#pragma unroll
        for (int j = 0; j < 4; j++) acc[i][j] = 0.0f;

    for (int kb = 0; kb < 8; kb++) {
        for (int i = tid; i < 64 * 32; i += 256) {
            int row = i >> 5, kk = i & 31;
            Esm[kk][row] = E[(v0 + row) * EMB + kb * 32 + kk];
            int gg   = g0 + row;
            int gate = gg >> 8, jj = gg & 255;
            int grow = (gate == 0 ? 0 : (gate == 1 ? 512 : 768)) + jj;
            Wsm[kk][row] = Ww[grow * 512 + 256 + kb * 32 + kk];
        }
        __syncthreads();
#pragma unroll
        for (int kk = 0; kk < 32; kk++) {
            float4 a4 = *(const float4*)&Esm[kk][ty * 4];
            float4 b4 = *(const float4*)&Wsm[kk][tx * 4];
            float av[4] = {a4.x, a4.y, a4.z, a4.w};
            float bv[4] = {b4.x, b4.y, b4.z, b4.w};
#pragma unroll
            for (int i = 0; i < 4; i++)
#pragma unroll
                for (int j = 0; j < 4; j++) acc[i][j] += av[i] * bv[j];
        }
        __syncthreads();
    }

#pragma unroll
    for (int i = 0; i < 4; i++) {
        int v = v0 + ty * 4 + i;
#pragma unroll
        for (int j = 0; j < 4; j++) {
            int g    = g0 + tx * 4 + j;
            int gate = g >> 8, jj = g & 255;
            int grow = (gate == 0 ? 0 : (gate == 1 ? 512 : 768)) + jj;
            g_T[v * G3 + g] = acc[i][j] + Wb[grow];
        }
    }
}

// ---------------------------------------------------------------------------
// Kernel 2: clustered persistent recurrence.
// ---------------------------------------------------------------------------

// dynamic SMEM layout (bytes)
#define SM_W     0         // ulonglong2 Wsm[64*96]        : 98304
#define SM_H     98304     // float4 Hsm[2][512]            : 16384  [r*64+k4]
#define SM_G     114688    // float  Gsm[16*96]             : 6144
#define SM_C     120832    // float  Csm[256]               : 1024
#define SM_HS    121856    // float  Hstage[256]            : 1024
#define SM_TOK   122880    // int    tokb[2][8]             : 64
#define SM_MBAR  122944    // uint64 mbar                   : 8
#define SMEM_TOTAL 122952

__global__ void __launch_bounds__(192, 1) __cluster_dims__(8, 1, 1)
lstm_kernel(const void* __restrict__ Xraw,
            const float* __restrict__ Ww,
            float* __restrict__ out)
{
    extern __shared__ char smem[];
    ulonglong2* Wsm    = (ulonglong2*)(smem + SM_W);
    float4*     Hsm4   = (float4*)(smem + SM_H);
    const ulonglong2* Hsm2 = (const ulonglong2*)(smem + SM_H);
    float*      Gsm    = (float*)(smem + SM_G);
    float*      Csm    = (float*)(smem + SM_C);
    float*      Hstage = (float*)(smem + SM_HS);
    int*        tokb   = (int*)(smem + SM_TOK);

    const uint32_t sbase = smem_u32(smem);
    const uint32_t mbar  = sbase + SM_MBAR;

    const int tid   = threadIdx.x;
    const uint32_t rank = ctarank();
    const int bt    = blockIdx.x >> 3;
    const int rb    = bt * 8;             // first batch row of this cluster
    const int j0    = (int)rank * 32;     // first hidden col of this CTA

    const int warp = tid >> 5;
    const int lane = tid & 31;
    const int cg   = warp % 3;            // 0=F, 1=O, 2=Htmp
    const int kh   = warp / 3;            // k half
    const int col  = cg * 32 + lane;      // 0..95

    // --- int64 vs int32 token buffer detection ----------------------------
    const int* Xi = (const int*)Xraw;
    bool is64 = true;
#pragma unroll
    for (int i = 0; i < 16; i++)
        if (Xi[2 * i + 1] != 0) is64 = false;
    const long long* Xl = (const long long*)Xraw;

    // --- load W_h slice, zero H buffer 0 and C state -----------------------
    for (int i = tid; i < 64 * 96; i += 192) {
        int k4 = i / 96, c = i % 96;
        int gsel = c >> 5, j = c & 31;
        int grow = (gsel == 0 ? 0 : (gsel == 1 ? 512 : 768)) + j0 + j;
        Wsm[i] = *(const ulonglong2*)(Ww + grow * 512 + k4 * 4);
    }
    for (int i = tid; i < 512; i += 192)
        Hsm4[i] = make_float4(0.f, 0.f, 0.f, 0.f);
    if (tid < 128) { Csm[tid] = 0.f; Csm[tid + 128] = 0.f; }
    if (tid == 0) mbar_init(mbar, 8);
    __syncthreads();
    cluster_sync_();   // mbarriers + zeroed H visible cluster-wide

    // tokens for t = 0
    if (tid < 8)
        tokb[tid] = is64 ? (int)Xl[(rb + tid) * LSEQ] : Xi[(rb + tid) * LSEQ];
    __syncthreads();

    for (int t = 0; t < LSEQ; t++) {
        const int cur = t & 1, nxt = cur ^ 1;

        // ---- Gx prefetch (input-determined; overlaps wait + k-loop) ------
        float gxF0 = 0.f, gxO0 = 0.f, gxH0 = 0.f;
        float gxF1 = 0.f, gxO1 = 0.f, gxH1 = 0.f;
        if (tid < 128) {
            const int e0 = tid, e1 = tid + 128;
            const float* T0 = g_T + (long long)tokb[cur * 8 + (e0 >> 5)] * G3
                              + j0 + (e0 & 31);
            const float* T1 = g_T + (long long)tokb[cur * 8 + (e1 >> 5)] * G3
                              + j0 + (e1 & 31);
            gxF0 = __ldg(T0);       gxO0 = __ldg(T0 + 256); gxH0 = __ldg(T0 + 512);
            gxF1 = __ldg(T1);       gxO1 = __ldg(T1 + 256); gxH1 = __ldg(T1 + 512);
        }
        // tokens for t+1 (read next iteration, after epilogue syncthreads)
        if (tid < 8 && t + 1 < LSEQ)
            tokb[nxt * 8 + tid] = is64 ? (int)Xl[(rb + tid) * LSEQ + t + 1]
                                       : Xi[(rb + tid) * LSEQ + t + 1];

        // ---- wait for peers' H pushes (phase t-1) -------------------------
        if (t > 0) mbar_wait_parity_cluster(mbar, (unsigned)(t - 1) & 1u);

        // ---- k-loop: partial G over this thread's k-half -------------------
        unsigned long long acc2[8];
#pragma unroll
        for (int r = 0; r < 8; r++) acc2[r] = 0ull;

        const ulonglong2* Hc = Hsm2 + cur * 512;
        const int kbase = kh * 32;
#pragma unroll 4
        for (int u = 0; u < 32; u++) {
            int kk4 = kbase + u;
            ulonglong2 wv = Wsm[kk4 * 96 + col];
#pragma unroll
            for (int r = 0; r < 8; r++) {
                ulonglong2 hv = Hc[r * 64 + kk4];
                acc2[r] = ffma2(wv.x, hv.x, acc2[r]);
                acc2[r] = ffma2(wv.y, hv.y, acc2[r]);
            }
        }
#pragma unroll
        for (int r = 0; r < 8; r++) {
            float2 f = ull2f2(acc2[r]);
            Gsm[(kh * 8 + r) * 96 + col] = f.x + f.y;
        }
        __syncthreads();

        // ---- epilogue: gates, C update, H_new (128 threads x 2 elems) -----
        if (tid < 128) {
#pragma unroll
            for (int half = 0; half < 2; half++) {
                int e = tid + half * 128;
                int r = e >> 5, j = e & 31;
                float gxF = half ? gxF1 : gxF0;
                float gxO = half ? gxO1 : gxO0;
                float gxH = half ? gxH1 : gxH0;
                float gF = Gsm[r * 96 + j]      + Gsm[(8 + r) * 96 + j]      + gxF;
                float gO = Gsm[r * 96 + 32 + j] + Gsm[(8 + r) * 96 + 32 + j] + gxO;
                float gH = Gsm[r * 96 + 64 + j] + Gsm[(8 + r) * 96 + 64 + j] + gxH;
                float F  = sig_fast(gF);
                float O  = sig_fast(gO);
                float Ht = tanh_fast(gH);
                float c  = F * Csm[e] + O * Ht;     // faithful: uses O, not I
                Csm[e] = c;
                float hn = O * tanh_fast(c);
                Hstage[e] = hn;
                if (t == LSEQ - 1)
                    out[(rb + r) * HDIM + j0 + j] = hn;
            }
        }
        __syncthreads();

        // ---- push H_new slice to all 8 cluster CTAs' Hsm[nxt] --------------
        {
            const float4* Hs4 = (const float4*)Hstage;
            for (int i = tid; i < 512; i += 192) {
                int dest = i >> 6, idx = i & 63;
                int r = idx >> 3, q = idx & 7;
                float4 v = Hs4[idx];
                uint32_t laddr = sbase + SM_H
                               + (uint32_t)(nxt * 8192
                                            + (r * 64 + (int)rank * 8 + q) * 16);
                st_cluster_128(mapa_u32(laddr, (uint32_t)dest), v);
            }
        }
        __syncthreads();

        // ---- arrive on every peer's mbarrier (phase t) ----------------------
        if (tid < 8) mbar_arrive_rank(mbar, (uint32_t)tid);
    }

    // consume the final phase so no CTA exits while peers' remote stores /
    // arrives targeting its SMEM are in flight
    mbar_wait_parity_cluster(mbar, (unsigned)(LSEQ - 1) & 1u);
}

// ---------------------------------------------------------------------------
// launcher
// ---------------------------------------------------------------------------
extern "C" void kernel_launch(void* const* d_in, const int* in_sizes, int n_in,
                              void* d_out, int out_size)
{
    (void)in_sizes; (void)n_in; (void)out_size;
    const void*  X   = d_in[0];
    const float* E   = (const float*)d_in[1];
    const float* Ww  = (const float*)d_in[2];
    const float* Wb  = (const float*)d_in[3];
    float*       out = (float*)d_out;

    cudaFuncSetAttribute(lstm_kernel,
                         cudaFuncAttributeMaxDynamicSharedMemorySize,
                         SMEM_TOTAL);

    table_kernel<<<dim3(VOC / 64, G3 / 64), 256>>>(E, Ww, Wb);
    lstm_kernel<<<128, 192, SMEM_TOTAL>>>(X, Ww, out);
}

// round 4
// speedup vs baseline: 1.9017x; 1.9017x over previous
#include <cuda_runtime.h>
#include <cstdint>

// ---------------------------------------------------------------------------
// SimpleLSTM on GB300 (sm_103a) — round 4: L2-exchange, per-group barriers,
// 3-gates-per-thread k-loop.
//
//   kernel 1 (table_kernel): token table T[v][g] = E[v] . W_x^T + b for the
//       768 LIVE gate rows (F, O, Htmp; the I gate is dead code). Block (0,0)
//       also zeroes the H double buffer and the 16 group counters.
//   kernel 2 (lstm_kernel): 128 persistent CTAs = 16 batch groups x 8
//       col-tiles. Groups are fully independent (CTA (bt,ct) needs H only
//       from the 8 CTAs sharing bt): each group has its own 8-arrival
//       monotonic counter in global memory (256B-strided). H is exchanged
//       through a global double buffer via st.cg / ld.cg. No threadfence:
//       st.cg -> __syncthreads -> red.add.release.gpu -> ld.acquire.gpu
//       gives transitive visibility.
// ---------------------------------------------------------------------------

#define NB    128
#define LSEQ  2048
#define HDIM  256
#define EMB   256
#define VOC   32000
#define G3    768
#define NT    256          // threads per lstm CTA (8 warps)

__device__ float    g_T[VOC * G3];          // token-gate table (~98.3 MB)
__device__ float    g_Hbuf[2][NB * HDIM];   // H double buffer
__device__ unsigned g_ctrs[16 * 64];        // per-group counters, 256B stride

// ---------------------------------------------------------------------------
// helpers
// ---------------------------------------------------------------------------
__device__ __forceinline__ unsigned long long ffma2(unsigned long long a,
                                                    unsigned long long b,
                                                    unsigned long long c)
{
    unsigned long long d;
    asm("fma.rn.f32x2 %0, %1, %2, %3;" : "=l"(d) : "l"(a), "l"(b), "l"(c));
    return d;
}

__device__ __forceinline__ float f2sum(unsigned long long v)
{
    float2 f;
    asm("mov.b64 {%0, %1}, %2;" : "=f"(f.x), "=f"(f.y) : "l"(v));
    return f.x + f.y;
}

__device__ __forceinline__ unsigned ld_acq(const unsigned* p)
{
    unsigned v;
    asm volatile("ld.acquire.gpu.u32 %0, [%1];" : "=r"(v) : "l"(p) : "memory");
    return v;
}

__device__ __forceinline__ void red_add_rel(unsigned* p, unsigned v)
{
    asm volatile("red.add.release.gpu.u32 [%0], %1;" :: "l"(p), "r"(v) : "memory");
}

__device__ __forceinline__ float sig_fast(float x)
{
    return __fdividef(1.0f, 1.0f + __expf(-x));
}

__device__ __forceinline__ float tanh_fast(float x)
{
    return __fdividef(2.0f, 1.0f + __expf(-2.0f * x)) - 1.0f;
}

// ---------------------------------------------------------------------------
// Kernel 1: token table GEMM (M=32000, N=768 live gates, K=256)
// ---------------------------------------------------------------------------
__global__ void table_kernel(const float* __restrict__ E,
                             const float* __restrict__ Ww,
                             const float* __restrict__ Wb)
{
    __shared__ float Esm[32][68];
    __shared__ float Wsm[32][68];

    const int tid = threadIdx.x;
    const int v0  = blockIdx.x * 64;
    const int g0  = blockIdx.y * 64;

    if (blockIdx.x == 0 && blockIdx.y == 0) {
        float* hb = (float*)g_Hbuf;
        for (int i = tid; i < 2 * NB * HDIM; i += 256) hb[i] = 0.0f;
        for (int i = tid; i < 16 * 64; i += 256) g_ctrs[i] = 0u;
    }

    const int tx = tid & 15;
    const int ty = tid >> 4;

    float acc[4][4];
#pragma unroll
    for (int i = 0; i < 4; i++)
#pragma unroll
        for (int j = 0; j < 4; j++) acc[i][j] = 0.0f;

    for (int kb = 0; kb < 8; kb++) {
        for (int i = tid; i < 64 * 32; i += 256) {
            int row = i >> 5, kk = i & 31;
            Esm[kk][row] = E[(v0 + row) * EMB + kb * 32 + kk];
            int gg   = g0 + row;
            int gate = gg >> 8, jj = gg & 255;
            int grow = (gate == 0 ? 0 : (gate == 1 ? 512 : 768)) + jj;
            Wsm[kk][row] = Ww[grow * 512 + 256 + kb * 32 + kk];
        }
        __syncthreads();
#pragma unroll
        for (int kk = 0; kk < 32; kk++) {
            float4 a4 = *(const float4*)&Esm[kk][ty * 4];
            float4 b4 = *(const float4*)&Wsm[kk][tx * 4];
            float av[4] = {a4.x, a4.y, a4.z, a4.w};
            float bv[4] = {b4.x, b4.y, b4.z, b4.w};
#pragma unroll
            for (int i = 0; i < 4; i++)
#pragma unroll
                for (int j = 0; j < 4; j++) acc[i][j] += av[i] * bv[j];
        }
        __syncthreads();
    }

#pragma unroll
    for (int i = 0; i < 4; i++) {
        int v = v0 + ty * 4 + i;
#pragma unroll
        for (int j = 0; j < 4; j++) {
            int g    = g0 + tx * 4 + j;
            int gate = g >> 8, jj = g & 255;
            int grow = (gate == 0 ? 0 : (gate == 1 ? 512 : 768)) + jj;
            g_T[v * G3 + g] = acc[i][j] + Wb[grow];
        }
    }
}

// ---------------------------------------------------------------------------
// Kernel 2: persistent recurrence.
//   CTA (bt = blockIdx.x>>3, ct = blockIdx.x&7): batch rows 8bt..8bt+7,
//   hidden cols 32ct..32ct+31 (and their F/O/Ht gate rows).
//   Thread map: warp = k-slice kq (8 slices of 8 k4), lane = hidden col j.
//   Each thread computes F, O, Ht partial dot-products for its j over its
//   k-slice for all 8 batch rows: one H broadcast feeds 6 FFMA2s.
// ---------------------------------------------------------------------------

// dynamic SMEM layout (bytes)
#define SM_W     0         // float4 Wsm[(k4*3+gate)*32 + j]   : 98304
#define SM_H     98304     // float4 Hsm[r*64 + k4]             : 8192
#define SM_G     106496    // float  Gsm[((kq*3+g)*8+r)*32+j]   : 24576
#define SM_C     131072    // float  Csm[256]                   : 1024
#define SM_TOK   132096    // int    tokb[2][8]                 : 64
#define SMEM_TOTAL 132160

__global__ void __launch_bounds__(NT, 1)
lstm_kernel(const void* __restrict__ Xraw,
            const float* __restrict__ Ww,
            float* __restrict__ out)
{
    extern __shared__ char smem[];
    float4*           Wsm4 = (float4*)(smem + SM_W);
    const ulonglong2* Wsm  = (const ulonglong2*)(smem + SM_W);
    float4*           Hsm4 = (float4*)(smem + SM_H);
    const ulonglong2* Hsm  = (const ulonglong2*)(smem + SM_H);
    float*            Gsm  = (float*)(smem + SM_G);
    float*            Csm  = (float*)(smem + SM_C);
    int*              tokb = (int*)(smem + SM_TOK);

    const int tid  = threadIdx.x;
    const int bt   = blockIdx.x >> 3;
    const int ct   = blockIdx.x & 7;
    const int rb   = bt * 8;
    const int j0   = ct * 32;

    const int kq   = tid >> 5;      // k-slice 0..7
    const int lane = tid & 31;      // hidden col within tile

    unsigned* ctr = &g_ctrs[bt * 64];

    // --- int64 vs int32 token buffer detection ----------------------------
    const int* Xi = (const int*)Xraw;
    bool is64 = true;
#pragma unroll
    for (int i = 0; i < 16; i++)
        if (Xi[2 * i + 1] != 0) is64 = false;
    const long long* Xl = (const long long*)Xraw;

    // --- load W slice: Wsm[(k4*3+gate)*32 + j] = W[grow(gate, j0+j)][4k4..]
    for (int i = tid; i < 96 * 64; i += NT) {
        int row = i >> 6, k4 = i & 63;       // row: gate*32 + j
        int gate = row >> 5, j = row & 31;
        int grow = (gate == 0 ? 0 : (gate == 1 ? 512 : 768)) + j0 + j;
        Wsm4[(k4 * 3 + gate) * 32 + j] = *(const float4*)(Ww + grow * 512 + k4 * 4);
    }
    if (tid < 256) Csm[tid] = 0.0f;
    if (tid < 8)
        tokb[tid] = is64 ? (int)Xl[(rb + tid) * LSEQ] : Xi[(rb + tid) * LSEQ];
    __syncthreads();

    for (int t = 0; t < LSEQ; t++) {
        const int cur = t & 1, nxt = cur ^ 1;

        // ---- Gx prefetch (token-determined; overlaps the wait) -----------
        const int er = tid >> 5, ej = tid & 31;   // epilogue element (r, j)
        const float* Tr = g_T + (long long)tokb[cur * 8 + er] * G3 + j0 + ej;
        float gxF = __ldg(Tr);
        float gxO = __ldg(Tr + 256);
        float gxH = __ldg(Tr + 512);

        // tokens for t+1
        if (tid < 8 && t + 1 < LSEQ)
            tokb[nxt * 8 + tid] = is64 ? (int)Xl[(rb + tid) * LSEQ + t + 1]
                                       : Xi[(rb + tid) * LSEQ + t + 1];

        // ---- wait for this group's 8 producers (step t) -------------------
        if (t > 0) {
            if (tid == 0) {
                unsigned target = 8u * (unsigned)t;
                while (ld_acq(ctr) < target) { }
            }
            __syncthreads();

            // ---- load H_t (8 x 256) from global into SMEM ----------------
            const float* hb = g_Hbuf[cur];
            for (int i = tid; i < 512; i += NT) {
                int r = i >> 6, k4 = i & 63;
                Hsm4[i] = __ldcg((const float4*)(hb + (rb + r) * HDIM + k4 * 4));
            }
            __syncthreads();
        } else {
            for (int i = tid; i < 512; i += NT)
                Hsm4[i] = make_float4(0.f, 0.f, 0.f, 0.f);
            __syncthreads();
        }

        // ---- k-loop: this thread's k-slice, 3 gates, 8 rows ---------------
        unsigned long long aF[8], aO[8], aH[8];
#pragma unroll
        for (int r = 0; r < 8; r++) { aF[r] = 0ull; aO[r] = 0ull; aH[r] = 0ull; }

        const int kb = kq * 8;
#pragma unroll 4
        for (int u = 0; u < 8; u++) {
            const int k4 = kb + u;
            ulonglong2 wF = Wsm[(k4 * 3 + 0) * 32 + lane];
            ulonglong2 wO = Wsm[(k4 * 3 + 1) * 32 + lane];
            ulonglong2 wH = Wsm[(k4 * 3 + 2) * 32 + lane];
#pragma unroll
            for (int r = 0; r < 8; r++) {
                ulonglong2 hv = Hsm[r * 64 + k4];
                aF[r] = ffma2(wF.x, hv.x, aF[r]);
                aF[r] = ffma2(wF.y, hv.y, aF[r]);
                aO[r] = ffma2(wO.x, hv.x, aO[r]);
                aO[r] = ffma2(wO.y, hv.y, aO[r]);
                aH[r] = ffma2(wH.x, hv.x, aH[r]);
                aH[r] = ffma2(wH.y, hv.y, aH[r]);
            }
        }
        // partials: Gsm[((kq*3+gate)*8 + r)*32 + j]  (conflict-free STS)
#pragma unroll
        for (int r = 0; r < 8; r++) {
            Gsm[((kq * 3 + 0) * 8 + r) * 32 + lane] = f2sum(aF[r]);
            Gsm[((kq * 3 + 1) * 8 + r) * 32 + lane] = f2sum(aO[r]);
            Gsm[((kq * 3 + 2) * 8 + r) * 32 + lane] = f2sum(aH[r]);
        }
        __syncthreads();

        // ---- epilogue: reduce 8 partials, gates, C, H_new ------------------
        {
            float gF = gxF, gO = gxO, gH = gxH;
#pragma unroll
            for (int q = 0; q < 8; q++) {
                gF += Gsm[((q * 3 + 0) * 8 + er) * 32 + ej];
                gO += Gsm[((q * 3 + 1) * 8 + er) * 32 + ej];
                gH += Gsm[((q * 3 + 2) * 8 + er) * 32 + ej];
            }
            float F  = sig_fast(gF);
            float O  = sig_fast(gO);
            float Ht = tanh_fast(gH);
            float c  = F * Csm[tid] + O * Ht;      // faithful: uses O, not I
            Csm[tid] = c;
            float hn = O * tanh_fast(c);
            __stcg(g_Hbuf[nxt] + (rb + er) * HDIM + j0 + ej, hn);
            if (t == LSEQ - 1)
                out[(rb + er) * HDIM + j0 + ej] = hn;
        }
        __syncthreads();   // all st.cg issued before the release-arrive

        // ---- arrive (release orders the CTA's prior stores transitively) --
        if (tid == 0) red_add_rel(ctr, 1u);
    }
}

// ---------------------------------------------------------------------------
// launcher
// ---------------------------------------------------------------------------
extern "C" void kernel_launch(void* const* d_in, const int* in_sizes, int n_in,
                              void* d_out, int out_size)
{
    (void)in_sizes; (void)n_in; (void)out_size;
    const void*  X   = d_in[0];
    const float* E   = (const float*)d_in[1];
    const float* Ww  = (const float*)d_in[2];
    const float* Wb  = (const float*)d_in[3];
    float*       out = (float*)d_out;

    cudaFuncSetAttribute(lstm_kernel,
                         cudaFuncAttributeMaxDynamicSharedMemorySize,
                         SMEM_TOTAL);

    table_kernel<<<dim3(VOC / 64, G3 / 64), 256>>>(E, Ww, Wb);
    lstm_kernel<<<128, NT, SMEM_TOTAL>>>(X, Ww, out);
}

// round 5
// speedup vs baseline: 2.2688x; 1.1931x over previous
#include <cuda_runtime.h>
#include <cstdint>

// ---------------------------------------------------------------------------
// SimpleLSTM on GB300 (sm_103a) — round 5: per-producer flags, per-warp
// waits/loads, self-slice via local SMEM staging.
//
//   kernel 1 (table_kernel): token table T[v][g] = E[v] . W_x^T + b for the
//       768 LIVE gate rows (F, O, Htmp; I gate is dead). Block (0,0) zeroes
//       the H double buffer and the 128 per-CTA flags. f32x2 inner product.
//   kernel 2 (lstm_kernel): 128 persistent CTAs = 16 groups x 8 col-tiles.
//       Warp kq of CTA (bt,ct) consumes exactly the H slice produced by CTA
//       (bt,kq): it waits on that CTA's private flag and loads its own 8x32
//       slice. kq==ct reads the locally staged slice (no L2). Block-wide
//       joins only at the partial-G reduction.
// ---------------------------------------------------------------------------

#define NB    128
#define LSEQ  2048
#define HDIM  256
#define EMB   256
#define VOC   32000
#define G3    768
#define NT    256

__device__ float    g_T[VOC * G3];          // token-gate table (~98.3 MB)
__device__ float    g_Hbuf[2][NB * HDIM];   // H double buffer
__device__ unsigned g_flags[128 * 64];      // per-CTA step flags, 256B stride

// ---------------------------------------------------------------------------
// helpers
// ---------------------------------------------------------------------------
__device__ __forceinline__ unsigned long long ffma2(unsigned long long a,
                                                    unsigned long long b,
                                                    unsigned long long c)
{
    unsigned long long d;
    asm("fma.rn.f32x2 %0, %1, %2, %3;" : "=l"(d) : "l"(a), "l"(b), "l"(c));
    return d;
}

__device__ __forceinline__ unsigned long long packf2(float lo, float hi)
{
    unsigned long long v;
    asm("mov.b64 %0, {%1, %2};" : "=l"(v) : "f"(lo), "f"(hi));
    return v;
}

__device__ __forceinline__ float f2sum(unsigned long long v)
{
    float2 f;
    asm("mov.b64 {%0, %1}, %2;" : "=f"(f.x), "=f"(f.y) : "l"(v));
    return f.x + f.y;
}

__device__ __forceinline__ unsigned ld_acq(const unsigned* p)
{
    unsigned v;
    asm volatile("ld.acquire.gpu.u32 %0, [%1];" : "=r"(v) : "l"(p) : "memory");
    return v;
}

__device__ __forceinline__ void red_add_rel(unsigned* p, unsigned v)
{
    asm volatile("red.add.release.gpu.u32 [%0], %1;" :: "l"(p), "r"(v) : "memory");
}

__device__ __forceinline__ float sig_fast(float x)
{
    return __fdividef(1.0f, 1.0f + __expf(-x));
}

__device__ __forceinline__ float tanh_fast(float x)
{
    return __fdividef(2.0f, 1.0f + __expf(-2.0f * x)) - 1.0f;
}

// ---------------------------------------------------------------------------
// Kernel 1: token table GEMM (M=32000, N=768 live gates, K=256)
// ---------------------------------------------------------------------------
__global__ void table_kernel(const float* __restrict__ E,
                             const float* __restrict__ Ww,
                             const float* __restrict__ Wb)
{
    __shared__ float Esm[32][68];
    __shared__ float Wsm[32][68];

    const int tid = threadIdx.x;
    const int v0  = blockIdx.x * 64;
    const int g0  = blockIdx.y * 64;

    if (blockIdx.x == 0 && blockIdx.y == 0) {
        float* hb = (float*)g_Hbuf;
        for (int i = tid; i < 2 * NB * HDIM; i += 256) hb[i] = 0.0f;
        for (int i = tid; i < 128 * 64; i += 256) g_flags[i] = 0u;
    }

    const int tx = tid & 15;
    const int ty = tid >> 4;

    unsigned long long acc2[4][2];
#pragma unroll
    for (int i = 0; i < 4; i++) { acc2[i][0] = 0ull; acc2[i][1] = 0ull; }

    for (int kb = 0; kb < 8; kb++) {
        for (int i = tid; i < 64 * 32; i += 256) {
            int row = i >> 5, kk = i & 31;
            Esm[kk][row] = E[(v0 + row) * EMB + kb * 32 + kk];
            int gg   = g0 + row;
            int gate = gg >> 8, jj = gg & 255;
            int grow = (gate == 0 ? 0 : (gate == 1 ? 512 : 768)) + jj;
            Wsm[kk][row] = Ww[grow * 512 + 256 + kb * 32 + kk];
        }
        __syncthreads();
#pragma unroll
        for (int kk = 0; kk < 32; kk++) {
            float4 a4 = *(const float4*)&Esm[kk][ty * 4];
            float4 b4 = *(const float4*)&Wsm[kk][tx * 4];
            unsigned long long blo = packf2(b4.x, b4.y);
            unsigned long long bhi = packf2(b4.z, b4.w);
            float av[4] = {a4.x, a4.y, a4.z, a4.w};
#pragma unroll
            for (int i = 0; i < 4; i++) {
                unsigned long long aa = packf2(av[i], av[i]);
                acc2[i][0] = ffma2(aa, blo, acc2[i][0]);
                acc2[i][1] = ffma2(aa, bhi, acc2[i][1]);
            }
        }
        __syncthreads();
    }

#pragma unroll
    for (int i = 0; i < 4; i++) {
        int v = v0 + ty * 4 + i;
#pragma unroll
        for (int jp = 0; jp < 2; jp++) {
            float2 f;
            asm("mov.b64 {%0, %1}, %2;" : "=f"(f.x), "=f"(f.y) : "l"(acc2[i][jp]));
            float fv[2] = {f.x, f.y};
#pragma unroll
            for (int s = 0; s < 2; s++) {
                int g    = g0 + tx * 4 + jp * 2 + s;
                int gate = g >> 8, jj = g & 255;
                int grow = (gate == 0 ? 0 : (gate == 1 ? 512 : 768)) + jj;
                g_T[v * G3 + g] = fv[s] + Wb[grow];
            }
        }
    }
}

// ---------------------------------------------------------------------------
// Kernel 2: persistent recurrence, per-warp producer waits.
// ---------------------------------------------------------------------------

// dynamic SMEM layout (bytes)
#define SM_W     0         // float4 Wsm[(k4*3+gate)*32 + j]   : 98304
#define SM_H     98304     // float4 Hsm[r*64 + k4]             : 8192
#define SM_G     106496    // float  Gsm[((kq*3+g)*8+r)*32+j]   : 24576
#define SM_C     131072    // float  Csm[256]                   : 1024
#define SM_HS    132096    // float  Hstage[256]                : 1024
#define SM_TOK   133120    // int    tokb[2][8]                 : 64
#define SMEM_TOTAL 133184

__global__ void __launch_bounds__(NT, 1)
lstm_kernel(const void* __restrict__ Xraw,
            const float* __restrict__ Ww,
            float* __restrict__ out)
{
    extern __shared__ char smem[];
    float4*           Wsm4   = (float4*)(smem + SM_W);
    const ulonglong2* Wsm    = (const ulonglong2*)(smem + SM_W);
    float4*           Hsm4   = (float4*)(smem + SM_H);
    const ulonglong2* Hsm    = (const ulonglong2*)(smem + SM_H);
    float*            Gsm    = (float*)(smem + SM_G);
    float*            Csm    = (float*)(smem + SM_C);
    float*            Hstage = (float*)(smem + SM_HS);
    const float4*     Hstage4 = (const float4*)(smem + SM_HS);
    int*              tokb   = (int*)(smem + SM_TOK);

    const int tid  = threadIdx.x;
    const int bt   = blockIdx.x >> 3;
    const int ct   = blockIdx.x & 7;
    const int rb   = bt * 8;
    const int j0   = ct * 32;

    const int kq   = tid >> 5;      // k-slice / producer CTA rank
    const int lane = tid & 31;

    unsigned* myflag   = &g_flags[(bt * 8 + ct) * 64];
    unsigned* prodflag = &g_flags[(bt * 8 + kq) * 64];

    // --- int64 vs int32 token buffer detection ----------------------------
    const int* Xi = (const int*)Xraw;
    bool is64 = true;
#pragma unroll
    for (int i = 0; i < 16; i++)
        if (Xi[2 * i + 1] != 0) is64 = false;
    const long long* Xl = (const long long*)Xraw;

    // --- load W slice: Wsm[(k4*3+gate)*32 + j] -----------------------------
    for (int i = tid; i < 96 * 64; i += NT) {
        int row = i >> 6, k4 = i & 63;
        int gate = row >> 5, j = row & 31;
        int grow = (gate == 0 ? 0 : (gate == 1 ? 512 : 768)) + j0 + j;
        Wsm4[(k4 * 3 + gate) * 32 + j] = *(const float4*)(Ww + grow * 512 + k4 * 4);
    }
    Csm[tid] = 0.0f;
    { // zero Hsm (used at t=0)
        for (int i = tid; i < 512; i += NT)
            Hsm4[i] = make_float4(0.f, 0.f, 0.f, 0.f);
    }
    if (tid < 8)
        tokb[tid] = is64 ? (int)Xl[(rb + tid) * LSEQ] : Xi[(rb + tid) * LSEQ];
    __syncthreads();

    // per-lane H slice mapping: elements i = lane, lane+32 -> (r = i>>3, q = i&7)
    const int r0 = lane >> 3,        q0 = lane & 7;
    const int r1 = (lane + 32) >> 3, q1 = lane & 7;

    for (int t = 0; t < LSEQ; t++) {
        const int cur = t & 1, nxt = cur ^ 1;

        // ---- Gx prefetch (token-determined; overlaps the wait) ------------
        const int er = kq, ej = lane;   // epilogue element (row, col) = (kq, lane)
        const float* Tr = g_T + (long long)tokb[cur * 8 + er] * G3 + j0 + ej;
        float gxF = __ldg(Tr);
        float gxO = __ldg(Tr + 256);
        float gxH = __ldg(Tr + 512);

        if (tid < 8 && t + 1 < LSEQ)
            tokb[nxt * 8 + tid] = is64 ? (int)Xl[(rb + tid) * LSEQ + t + 1]
                                       : Xi[(rb + tid) * LSEQ + t + 1];

        // ---- per-warp: wait for producer CTA (bt,kq), load 8x32 H slice ---
        if (t > 0) {
            if (kq == ct) {
                // self slice: staged locally last step (ordered by sync B)
                Hsm4[r0 * 64 + kq * 8 + q0] = Hstage4[r0 * 8 + q0];
                Hsm4[r1 * 64 + kq * 8 + q1] = Hstage4[r1 * 8 + q1];
            } else {
                unsigned target = (unsigned)t;
                while (ld_acq(prodflag) < target) { }
                const float* hb = g_Hbuf[cur];
                float4 v0 = __ldcg((const float4*)(hb + (rb + r0) * HDIM + kq * 32 + q0 * 4));
                float4 v1 = __ldcg((const float4*)(hb + (rb + r1) * HDIM + kq * 32 + q1 * 4));
                Hsm4[r0 * 64 + kq * 8 + q0] = v0;
                Hsm4[r1 * 64 + kq * 8 + q1] = v1;
            }
            __syncwarp();
        }

        // ---- k-loop: this warp's k-slice, 3 gates, 8 rows ------------------
        unsigned long long aF[8], aO[8], aH[8];
#pragma unroll
        for (int r = 0; r < 8; r++) { aF[r] = 0ull; aO[r] = 0ull; aH[r] = 0ull; }

        const int kb = kq * 8;
#pragma unroll 4
        for (int u = 0; u < 8; u++) {
            const int k4 = kb + u;
            ulonglong2 wF = Wsm[(k4 * 3 + 0) * 32 + lane];
            ulonglong2 wO = Wsm[(k4 * 3 + 1) * 32 + lane];
            ulonglong2 wH = Wsm[(k4 * 3 + 2) * 32 + lane];
#pragma unroll
            for (int r = 0; r < 8; r++) {
                ulonglong2 hv = Hsm[r * 64 + k4];
                aF[r] = ffma2(wF.x, hv.x, aF[r]);
                aF[r] = ffma2(wF.y, hv.y, aF[r]);
                aO[r] = ffma2(wO.x, hv.x, aO[r]);
                aO[r] = ffma2(wO.y, hv.y, aO[r]);
                aH[r] = ffma2(wH.x, hv.x, aH[r]);
                aH[r] = ffma2(wH.y, hv.y, aH[r]);
            }
        }
#pragma unroll
        for (int r = 0; r < 8; r++) {
            Gsm[((kq * 3 + 0) * 8 + r) * 32 + lane] = f2sum(aF[r]);
            Gsm[((kq * 3 + 1) * 8 + r) * 32 + lane] = f2sum(aO[r]);
            Gsm[((kq * 3 + 2) * 8 + r) * 32 + lane] = f2sum(aH[r]);
        }
        __syncthreads();   // (A) join for the cross-warp reduction

        // ---- epilogue: reduce 8 partials, gates, C, H_new -------------------
        {
            float gF = gxF, gO = gxO, gH = gxH;
#pragma unroll
            for (int q = 0; q < 8; q++) {
                gF += Gsm[((q * 3 + 0) * 8 + er) * 32 + ej];
                gO += Gsm[((q * 3 + 1) * 8 + er) * 32 + ej];
                gH += Gsm[((q * 3 + 2) * 8 + er) * 32 + ej];
            }
            float F  = sig_fast(gF);
            float O  = sig_fast(gO);
            float Ht = tanh_fast(gH);
            float c  = F * Csm[tid] + O * Ht;      // faithful: uses O, not I
            Csm[tid] = c;
            float hn = O * tanh_fast(c);
            Hstage[er * 32 + ej] = hn;                       // self-slice stage
            __stcg(g_Hbuf[nxt] + (rb + er) * HDIM + j0 + ej, hn);
            if (t == LSEQ - 1)
                out[(rb + er) * HDIM + j0 + ej] = hn;
        }
        __syncthreads();   // (B) st.cg + Hstage complete before arrive / reuse

        // ---- arrive: flag = t+1 (release orders this CTA's prior stores) ---
        if (tid == 0) red_add_rel(myflag, 1u);
    }
}

// ---------------------------------------------------------------------------
// launcher
// ---------------------------------------------------------------------------
extern "C" void kernel_launch(void* const* d_in, const int* in_sizes, int n_in,
                              void* d_out, int out_size)
{
    (void)in_sizes; (void)n_in; (void)out_size;
    const void*  X   = d_in[0];
    const float* E   = (const float*)d_in[1];
    const float* Ww  = (const float*)d_in[2];
    const float* Wb  = (const float*)d_in[3];
    float*       out = (float*)d_out;

    cudaFuncSetAttribute(lstm_kernel,
                         cudaFuncAttributeMaxDynamicSharedMemorySize,
                         SMEM_TOTAL);

    table_kernel<<<dim3(VOC / 64, G3 / 64), 256>>>(E, Ww, Wb);
    lstm_kernel<<<128, NT, SMEM_TOTAL>>>(X, Ww, out);
}